// round 4
// baseline (speedup 1.0000x reference)
#include <cuda_runtime.h>
#include <cuda_fp16.h>
#include <cstdint>

#define TT        10
#define NB        32                 // batch rows per CTA
#define THREADS   512
#define NCTA      (65536 / NB)       // 2048

// smem layout (bytes)
#define XH_OFF    0                  // x hi plane: 512 k-rows x 32 n x 2B = 32KB
#define XL_OFF    32768
#define W_OFF     65536              // 4-slot ring of 32KB W chunks
#define SMEM_TOTAL (65536 + 4 * 32768)   // 192KB

// W chunk stream: chunk = K16 slab; row p (512 rows) = [16 hi halfs | 16 lo halfs] = 64B,
// pre-swizzled with swz64. Wa: 16 chunks (K=256), Wb: 32 chunks (K=512).
#define CHUNK_HALFS 16384            // 32KB
#define NCH_TOTAL   (16 + 10 * 32)   // 336 chunks in the global stream
__device__ __half g_Wa[16 * CHUNK_HALFS];   // 512KB
__device__ __half g_Wb[32 * CHUNK_HALFS];   // 1MB

// ---------------- PTX helpers ----------------
static __device__ __forceinline__ uint32_t smem_u32(const void* p) {
    uint32_t a;
    asm("{ .reg .u64 t; cvta.to.shared.u64 t, %1; cvt.u32.u64 %0, t; }" : "=r"(a) : "l"(p));
    return a;
}
static __device__ __forceinline__ void cp16(uint32_t s, const void* g) {
    asm volatile("cp.async.cg.shared.global [%0], [%1], 16;" :: "r"(s), "l"(g));
}
static __device__ __forceinline__ void ldmA4(uint32_t* r, uint32_t addr) {
    asm volatile("ldmatrix.sync.aligned.m8n8.x4.shared.b16 {%0,%1,%2,%3}, [%4];"
                 : "=r"(r[0]), "=r"(r[1]), "=r"(r[2]), "=r"(r[3]) : "r"(addr));
}
static __device__ __forceinline__ void ldmB4(uint32_t* r, uint32_t addr) {
    asm volatile("ldmatrix.sync.aligned.m8n8.x4.trans.shared.b16 {%0,%1,%2,%3}, [%4];"
                 : "=r"(r[0]), "=r"(r[1]), "=r"(r[2]), "=r"(r[3]) : "r"(addr));
}
static __device__ __forceinline__ void mma16816(float* d, const uint32_t* a, const uint32_t* b) {
    asm volatile("mma.sync.aligned.m16n8k16.row.col.f32.f16.f16.f32 "
                 "{%0,%1,%2,%3}, {%4,%5,%6,%7}, {%8,%9}, {%0,%1,%2,%3};"
                 : "+f"(d[0]), "+f"(d[1]), "+f"(d[2]), "+f"(d[3])
                 : "r"(a[0]), "r"(a[1]), "r"(a[2]), "r"(a[3]), "r"(b[0]), "r"(b[1]));
}

// Swizzle for 64B rows: XOR 16B-slot bits [5:4] with row bits [2:1].
static __device__ __host__ __forceinline__ uint32_t swz64(int row, int colbyte) {
    return (uint32_t)(row * 64 + (colbyte ^ ((row & 6) << 3)));
}

// ---------------- prep: expand complex A,B -> packed hi/lo K16 chunks ----------------
__global__ void prep_kernel(const float* __restrict__ A, const float* __restrict__ B) {
    const int NB_EL = 512 * 512;     // B expanded elements
    const int NA_EL = 512 * 256;
    for (int i = blockIdx.x * blockDim.x + threadIdx.x; i < NB_EL + NA_EL;
         i += gridDim.x * blockDim.x) {
        float v;
        __half* dst;
        int p, k;
        if (i < NB_EL) {
            p = i >> 9; k = i & 511;
            if (k < 256) v = (p < 256) ? B[p * 256 + k] : B[65536 + (p - 256) * 256 + k];
            else { int q = k - 256; v = (p < 256) ? -B[65536 + p * 256 + q] : B[(p - 256) * 256 + q]; }
            dst = g_Wb + (size_t)(k >> 4) * CHUNK_HALFS;
        } else {
            int j = i - NB_EL;
            p = j >> 8; k = j & 255;
            if (k < 128) v = (p < 256) ? A[p * 128 + k] : A[32768 + (p - 256) * 128 + k];
            else { int q = k - 128; v = (p < 256) ? -A[32768 + p * 128 + q] : A[(p - 256) * 128 + q]; }
            dst = g_Wa + (size_t)(k >> 4) * CHUNK_HALFS;
        }
        const int kk = k & 15;
        __half hi = __float2half_rn(v);
        __half lo = __float2half_rn(v - __half2float(hi));
        dst[swz64(p, kk * 2) >> 1] = hi;
        dst[swz64(p, 32 + kk * 2) >> 1] = lo;
    }
}

static __device__ __forceinline__ const __half* chunk_ptr(int gi) {
    return (gi < 16) ? g_Wa + (size_t)gi * CHUNK_HALFS
                     : g_Wb + (size_t)((gi - 16) & 31) * CHUNK_HALFS;
}
static __device__ __forceinline__ void issue_chunk(uint32_t dst, const __half* src, int tid) {
    const char* s = (const char*)src + tid * 64;
    uint32_t d = dst + (uint32_t)tid * 64;
    cp16(d,      s);
    cp16(d + 16, s + 16);
    cp16(d + 32, s + 32);
    cp16(d + 48, s + 48);
}

// ---------------- main fused kernel ----------------
__global__ __launch_bounds__(THREADS, 1)
void lista_main(const float* __restrict__ y,
                const float* __restrict__ etas,
                const float* __restrict__ gammas,
                float* __restrict__ out) {
    extern __shared__ char smc[];
    const uint32_t smb = smem_u32(smc);
    const int tid = threadIdx.x, lane = tid & 31, wid = tid >> 5;
    const int mbase = wid * 32;                // warp owns M rows [mbase, mbase+32)
    const long b0 = (long)blockIdx.x * NB;

    // stage y into x planes (k rows 0..255): k = c*128 + q
    for (int idx = tid; idx < NB * 256; idx += THREADS) {
        int n = idx >> 8, j = idx & 255, q = j >> 1, cc = j & 1, k = cc * 128 + q;
        float v = y[(b0 + n) * 256 + j];
        __half hi = __float2half_rn(v);
        __half lo = __float2half_rn(v - __half2float(hi));
        uint32_t off = swz64(k, n * 2);
        *(__half*)(smc + XH_OFF + off) = hi;
        *(__half*)(smc + XL_OFF + off) = lo;
    }
    // (visibility guaranteed by the barrier inside the first chunk step)

    // prologue: prefetch chunks 0..2 (one commit group each)
    for (int c = 0; c < 3; ++c) {
        issue_chunk(smb + W_OFF + (uint32_t)c * 32768, chunk_ptr(c), tid);
        asm volatile("cp.async.commit_group;" ::: "memory");
    }

    // lane geometry for operand loads
    const int l15 = lane & 15;
    const uint32_t axor = (uint32_t)((l15 & 6) << 3);
    const uint32_t bxor = (uint32_t)((lane & 6) << 3);
    uint32_t abase[2];
#pragma unroll
    for (int mt = 0; mt < 2; ++mt) abase[mt] = (uint32_t)(mbase + mt * 16 + l15) * 64;
    const uint32_t ahcol = (((uint32_t)(lane >> 4) * 16)) ^ axor;
    const uint32_t alcol = (32u + (uint32_t)(lane >> 4) * 16) ^ axor;
    const uint32_t brow  = ((uint32_t)(lane & 7) + ((uint32_t)((lane >> 3) & 1)) * 8) * 64;
    const uint32_t bcol0 = (((uint32_t)(lane >> 4) * 16)) ^ bxor;       // n 0..15
    const uint32_t bcol1 = (32u + (uint32_t)(lane >> 4) * 16) ^ bxor;   // n 16..31

    // epilogue lane geometry
    const int eg = lane >> 2, ec = lane & 3;
    const uint32_t exor = (uint32_t)((eg & 6) << 3);

    float ay[32], d[32];   // acc index: (mt*4 + nt)*4 + r

    int gi = 0;
#pragma unroll 1
    for (int pass = 0; pass <= TT; ++pass) {
        const int nc = pass ? 32 : 16;
#pragma unroll
        for (int r = 0; r < 32; ++r) d[r] = 0.0f;

#pragma unroll 1
        for (int c = 0; c < nc; ++c, ++gi) {
            asm volatile("cp.async.wait_group 2;" ::: "memory");
            __syncthreads();
            // prefetch gi+3 into slot (gi+3)&3 == (gi-1)&3 (safe: all reads of gi-1 done)
            const int pf = gi + 3;
            if (pf < NCH_TOTAL)
                issue_chunk(smb + W_OFF + (uint32_t)(pf & 3) * 32768, chunk_ptr(pf), tid);
            asm volatile("cp.async.commit_group;" ::: "memory");

            const uint32_t wb = smb + W_OFF + (uint32_t)(gi & 3) * 32768;
            const uint32_t xr = smb + XH_OFF + (uint32_t)c * 1024 + brow;

            uint32_t bh[8], bl[8];           // [nt*2 + reg]
            ldmB4(bh,     xr + bcol0);
            ldmB4(bh + 4, xr + bcol1);
            ldmB4(bl,     xr + 32768 + bcol0);
            ldmB4(bl + 4, xr + 32768 + bcol1);
            uint32_t ah[2][4], al[2][4];
            ldmA4(ah[0], wb + abase[0] + ahcol);
            ldmA4(ah[1], wb + abase[1] + ahcol);
            ldmA4(al[0], wb + abase[0] + alcol);
            ldmA4(al[1], wb + abase[1] + alcol);

            // term-major MMA order: 8 independent accs between dependent MMAs
#pragma unroll
            for (int mt = 0; mt < 2; ++mt)
#pragma unroll
                for (int nt = 0; nt < 4; ++nt)
                    mma16816(&d[(mt * 4 + nt) * 4], ah[mt], &bh[nt * 2]);   // Wh*xh
#pragma unroll
            for (int mt = 0; mt < 2; ++mt)
#pragma unroll
                for (int nt = 0; nt < 4; ++nt)
                    mma16816(&d[(mt * 4 + nt) * 4], ah[mt], &bl[nt * 2]);   // Wh*xl
#pragma unroll
            for (int mt = 0; mt < 2; ++mt)
#pragma unroll
                for (int nt = 0; nt < 4; ++nt)
                    mma16816(&d[(mt * 4 + nt) * 4], al[mt], &bh[nt * 2]);   // Wl*xh
        }

        __syncthreads();   // all warps done reading x planes before epilogue overwrites

        const float g = gammas[pass], e = etas[pass];
        if (pass == 0) {
#pragma unroll
            for (int r = 0; r < 32; ++r) ay[r] = d[r];
        }
#pragma unroll
        for (int mt = 0; mt < 2; ++mt)
#pragma unroll
            for (int nt = 0; nt < 4; ++nt)
#pragma unroll
                for (int rg = 0; rg < 2; ++rg) {
                    const int p = mbase + mt * 16 + eg + rg * 8;
                    const uint32_t off = (uint32_t)p * 64
                                       + (((uint32_t)(16 * nt + 4 * ec)) ^ exor);
                    const int ai = (mt * 4 + nt) * 4 + rg * 2;
                    float v0, v1;
                    if (pass == 0) {
                        v0 = g * ay[ai];
                        v1 = g * ay[ai + 1];
                    } else {
                        __half2 hh = *(const __half2*)(smc + XH_OFF + off);
                        __half2 ll = *(const __half2*)(smc + XL_OFF + off);
                        float2 fh = __half22float2(hh), fl = __half22float2(ll);
                        v0 = fmaf(g, ay[ai]     - d[ai],     fh.x + fl.x);
                        v1 = fmaf(g, ay[ai + 1] - d[ai + 1], fh.y + fl.y);
                    }
                    float x0 = copysignf(fmaxf(fabsf(v0) - e, 0.0f), v0);
                    float x1 = copysignf(fmaxf(fabsf(v1) - e, 0.0f), v1);
                    __half h0 = __float2half_rn(x0), h1 = __float2half_rn(x1);
                    __half l0 = __float2half_rn(x0 - __half2float(h0));
                    __half l1 = __float2half_rn(x1 - __half2float(h1));
                    *(__half2*)(smc + XH_OFF + off) = __halves2half2(h0, h1);
                    *(__half2*)(smc + XL_OFF + off) = __halves2half2(l0, l1);
                }
        // next pass's first chunk barrier orders these writes vs ldmatrix reads
    }

    __syncthreads();
    // output: out[b][m][c] = x[p = c*256 + m], coalesced fp32 writes
    for (int idx = tid; idx < NB * 512; idx += THREADS) {
        const int n = idx >> 9, i = idx & 511, m = i >> 1, cc = i & 1;
        const int p = cc * 256 + m;
        const uint32_t off = swz64(p, n * 2);
        const float v = __half2float(*(const __half*)(smc + XH_OFF + off))
                      + __half2float(*(const __half*)(smc + XL_OFF + off));
        out[(b0 + n) * 512 + i] = v;
    }
}

extern "C" void kernel_launch(void* const* d_in, const int* in_sizes, int n_in,
                              void* d_out, int out_size) {
    const float* y      = (const float*)d_in[0];
    const float* A      = (const float*)d_in[1];
    const float* B      = (const float*)d_in[2];
    const float* etas   = (const float*)d_in[3];
    const float* gammas = (const float*)d_in[4];
    float* out = (float*)d_out;

    prep_kernel<<<512, 256>>>(A, B);

    cudaFuncSetAttribute(lista_main, cudaFuncAttributeMaxDynamicSharedMemorySize, SMEM_TOTAL);
    lista_main<<<NCTA, THREADS, SMEM_TOTAL>>>(y, etas, gammas, out);
}

// round 5
// speedup vs baseline: 1.5225x; 1.5225x over previous
#include <cuda_runtime.h>
#include <cuda_fp16.h>
#include <cstdint>

#define TT        10
#define NB        32                 // batch rows per CTA
#define THREADS   512
#define NCTA      (65536 / NB)       // 2048

// smem layout (bytes)
#define XH_OFF    0                  // x hi: 512 k-rows x 32 n x 2B = 32KB
#define XL_OFF    32768
#define W_OFF     65536              // 2 bufs x (Wh 32KB + Wl 32KB)
#define SMEM_TOTAL (65536 + 2 * 65536)   // 192KB

// W chunk arrays, pre-swizzled: chunk = K-slab of 32, layout [p=512][kk=32] halves
__device__ __half g_WbH[16 * 16384];   // 512KB
__device__ __half g_WbL[16 * 16384];
__device__ __half g_WaH[8 * 16384];    // 256KB
__device__ __half g_WaL[8 * 16384];

// ---------------- PTX helpers ----------------
static __device__ __forceinline__ uint32_t smem_u32(const void* p) {
    uint32_t a;
    asm("{ .reg .u64 t; cvta.to.shared.u64 t, %1; cvt.u32.u64 %0, t; }" : "=r"(a) : "l"(p));
    return a;
}
static __device__ __forceinline__ void cp16(uint32_t s, const void* g) {
    asm volatile("cp.async.cg.shared.global [%0], [%1], 16;" :: "r"(s), "l"(g));
}
static __device__ __forceinline__ void ldmA4(uint32_t* r, uint32_t addr) {
    asm volatile("ldmatrix.sync.aligned.m8n8.x4.shared.b16 {%0,%1,%2,%3}, [%4];"
                 : "=r"(r[0]), "=r"(r[1]), "=r"(r[2]), "=r"(r[3]) : "r"(addr));
}
static __device__ __forceinline__ void ldmB4(uint32_t* r, uint32_t addr) {
    asm volatile("ldmatrix.sync.aligned.m8n8.x4.trans.shared.b16 {%0,%1,%2,%3}, [%4];"
                 : "=r"(r[0]), "=r"(r[1]), "=r"(r[2]), "=r"(r[3]) : "r"(addr));
}
static __device__ __forceinline__ void mma16816(float* d, const uint32_t* a, const uint32_t* b) {
    asm volatile("mma.sync.aligned.m16n8k16.row.col.f32.f16.f16.f32 "
                 "{%0,%1,%2,%3}, {%4,%5,%6,%7}, {%8,%9}, {%0,%1,%2,%3};"
                 : "+f"(d[0]), "+f"(d[1]), "+f"(d[2]), "+f"(d[3])
                 : "r"(a[0]), "r"(a[1]), "r"(a[2]), "r"(a[3]), "r"(b[0]), "r"(b[1]));
}

// Swizzle for 64B rows: XOR 16B-slot bits [5:4] with row bits [2:1].
static __device__ __host__ __forceinline__ uint32_t swz64(int row, int colbyte) {
    return (uint32_t)(row * 64 + (colbyte ^ ((row & 6) << 3)));
}

// ---------------- prep: expand complex A,B -> fp16 hi/lo swizzled chunks ----------------
__global__ void prep_kernel(const float* __restrict__ A, const float* __restrict__ B) {
    for (int i = blockIdx.x * blockDim.x + threadIdx.x; i < 393216;
         i += gridDim.x * blockDim.x) {
        float v;
        int dest;
        __half *dH, *dL;
        if (i < 262144) {                        // B matrix: 16 chunks
            int chunk = i >> 14, inner = i & 16383, p = inner >> 5, kk = inner & 31;
            int k = chunk * 32 + kk;
            if (k < 256) v = (p < 256) ? B[p * 256 + k] : B[65536 + (p - 256) * 256 + k];
            else { int q = k - 256; v = (p < 256) ? -B[65536 + p * 256 + q] : B[(p - 256) * 256 + q]; }
            dest = chunk * 16384 + (int)(swz64(p, kk * 2) >> 1);
            dH = g_WbH; dL = g_WbL;
        } else {                                  // A matrix: 8 chunks
            int j = i - 262144;
            int chunk = j >> 14, inner = j & 16383, p = inner >> 5, kk = inner & 31;
            int k = chunk * 32 + kk;
            if (k < 128) v = (p < 256) ? A[p * 128 + k] : A[32768 + (p - 256) * 128 + k];
            else { int q = k - 128; v = (p < 256) ? -A[32768 + p * 128 + q] : A[(p - 256) * 128 + q]; }
            dest = chunk * 16384 + (int)(swz64(p, kk * 2) >> 1);
            dH = g_WaH; dL = g_WaL;
        }
        __half hi = __float2half_rn(v);
        dH[dest] = hi;
        dL[dest] = __float2half_rn(v - __half2float(hi));
    }
}

// ---------------- chunk loader: 64KB (Wh + Wl) via cp.async ----------------
static __device__ __forceinline__ void issue_chunk(uint32_t sbuf, const __half* gH,
                                                   const __half* gL, int c, int tid) {
    const char* srcH = (const char*)gH + (size_t)c * 32768;
    const char* srcL = (const char*)gL + (size_t)c * 32768;
#pragma unroll
    for (int u = 0; u < 4; ++u) {
        uint32_t o = (uint32_t)tid * 16 + (uint32_t)u * 8192;
        cp16(sbuf + o, srcH + o);
        cp16(sbuf + 32768 + o, srcL + o);
    }
}

// ---------------- GEMM pass: acc[p-tile][n-tile] += 3-term split W*x ----------------
static __device__ __forceinline__ void gemm_pass(
    uint32_t smb, const __half* gH, const __half* gL, int NC,
    float (*acc)[4], int mbase, int nbase, int tid, int lane)
{
    issue_chunk(smb + W_OFF, gH, gL, 0, tid);
    asm volatile("cp.async.commit_group;" ::: "memory");
    issue_chunk(smb + W_OFF + 65536, gH, gL, 1, tid);
    asm volatile("cp.async.commit_group;" ::: "memory");

    const int l15 = lane & 15;
    const uint32_t axor = (uint32_t)((l15 & 6) << 3);

    // A ldmatrix offsets within a W chunk buffer: 4 mtiles x 2 ksteps
    uint32_t aoff[4][2];
#pragma unroll
    for (int mt = 0; mt < 4; ++mt)
#pragma unroll
        for (int s = 0; s < 2; ++s)
            aoff[mt][s] = (uint32_t)(mbase + mt * 16 + l15) * 64
                        + (((uint32_t)(s * 32 + ((lane >> 4) * 16))) ^ axor);

    // B column-byte selector for x4.trans: lanes 0-15 -> n[nbase..+8), 16-31 -> n[+8..+16)
    const uint32_t bcolsel = ((uint32_t)(nbase * 2) + ((uint32_t)(lane >> 4) * 16)) ^ axor;

#pragma unroll 1
    for (int c = 0; c < NC; ++c) {
        asm volatile("cp.async.wait_group 1;" ::: "memory");
        __syncthreads();
        const uint32_t wb = smb + W_OFF + (uint32_t)(c & 1) * 65536;
#pragma unroll
        for (int s = 0; s < 2; ++s) {
            const uint32_t krow = (uint32_t)(c * 32 + s * 16 + l15) * 64;
            uint32_t bh[4], bl[4];
            ldmB4(bh, smb + XH_OFF + krow + bcolsel);
            ldmB4(bl, smb + XL_OFF + krow + bcolsel);
#pragma unroll
            for (int mp = 0; mp < 2; ++mp) {
                uint32_t ah[2][4], al[2][4];
                ldmA4(ah[0], wb + aoff[mp * 2 + 0][s]);
                ldmA4(ah[1], wb + aoff[mp * 2 + 1][s]);
                ldmA4(al[0], wb + 32768 + aoff[mp * 2 + 0][s]);
                ldmA4(al[1], wb + 32768 + aoff[mp * 2 + 1][s]);
                // term-major: 4 independent accumulators between same-acc reuse
#pragma unroll
                for (int m2 = 0; m2 < 2; ++m2)
#pragma unroll
                    for (int nt = 0; nt < 2; ++nt)
                        mma16816(acc[(mp * 2 + m2) * 2 + nt], ah[m2], &bh[nt * 2]); // Wh*xh
#pragma unroll
                for (int m2 = 0; m2 < 2; ++m2)
#pragma unroll
                    for (int nt = 0; nt < 2; ++nt)
                        mma16816(acc[(mp * 2 + m2) * 2 + nt], ah[m2], &bl[nt * 2]); // Wh*xl
#pragma unroll
                for (int m2 = 0; m2 < 2; ++m2)
#pragma unroll
                    for (int nt = 0; nt < 2; ++nt)
                        mma16816(acc[(mp * 2 + m2) * 2 + nt], al[m2], &bh[nt * 2]); // Wl*xh
            }
        }
        __syncthreads();
        if (c + 2 < NC) issue_chunk(wb, gH, gL, c + 2, tid);
        asm volatile("cp.async.commit_group;" ::: "memory");
    }
}

// ---------------- main fused kernel ----------------
__global__ __launch_bounds__(THREADS, 1)
void lista_main(const float* __restrict__ y,
                const float* __restrict__ etas,
                const float* __restrict__ gammas,
                float* __restrict__ out) {
    extern __shared__ char smc[];
    const uint32_t smb = smem_u32(smc);
    const int tid = threadIdx.x, lane = tid & 31, wid = tid >> 5;
    const int mbase = (wid >> 1) * 64;        // 8 M-warps x 64 rows
    const int nbase = (wid & 1) * 16;         // 2 N-warps x 16 cols
    const long b0 = (long)blockIdx.x * NB;

    // stage y into x planes (rows 0..255): k = c*128 + q
    for (int idx = tid; idx < NB * 256; idx += THREADS) {
        int n = idx >> 8, j = idx & 255, q = j >> 1, cc = j & 1, k = cc * 128 + q;
        float v = y[(b0 + n) * 256 + j];
        __half hi = __float2half_rn(v);
        __half lo = __float2half_rn(v - __half2float(hi));
        uint32_t off = swz64(k, n * 2);
        *(__half*)(smc + XH_OFF + off) = hi;
        *(__half*)(smc + XL_OFF + off) = lo;
    }
    __syncthreads();

    float ay[8][4], d[8][4];
#pragma unroll
    for (int i = 0; i < 8; ++i)
#pragma unroll
        for (int j = 0; j < 4; ++j) ay[i][j] = 0.0f;

    // epilogue lane geometry
    const int eg = lane >> 2, ec = lane & 3;
    const uint32_t exor = (uint32_t)((eg & 6) << 3);

    // -------- Phase A: Ay = Wa * y (resident in regs) --------
    gemm_pass(smb, g_WaH, g_WaL, 8, ay, mbase, nbase, tid, lane);
    {
        const float g = gammas[0], e = etas[0];
#pragma unroll
        for (int mt = 0; mt < 4; ++mt)
#pragma unroll
            for (int nt = 0; nt < 2; ++nt)
#pragma unroll
                for (int rg = 0; rg < 2; ++rg) {
                    const int p = mbase + mt * 16 + eg + rg * 8;
                    const uint32_t ncb = (uint32_t)((nbase + nt * 8) * 2 + ec * 4);
                    const uint32_t off = (uint32_t)p * 64 + (ncb ^ exor);
                    const int ai = mt * 2 + nt;
                    float v0 = g * ay[ai][rg * 2 + 0];
                    float v1 = g * ay[ai][rg * 2 + 1];
                    float x0 = copysignf(fmaxf(fabsf(v0) - e, 0.0f), v0);
                    float x1 = copysignf(fmaxf(fabsf(v1) - e, 0.0f), v1);
                    __half h0 = __float2half_rn(x0), h1 = __float2half_rn(x1);
                    __half l0 = __float2half_rn(x0 - __half2float(h0));
                    __half l1 = __float2half_rn(x1 - __half2float(h1));
                    *(__half2*)(smc + XH_OFF + off) = __halves2half2(h0, h1);
                    *(__half2*)(smc + XL_OFF + off) = __halves2half2(l0, l1);
                }
    }
    // next gemm's first barrier orders these writes vs ldmatrix reads

    // -------- 10 iterations: x = shrink(x + g*(Ay - Bx), e) --------
#pragma unroll 1
    for (int t = 1; t <= TT; ++t) {
#pragma unroll
        for (int i = 0; i < 8; ++i)
#pragma unroll
            for (int j = 0; j < 4; ++j) d[i][j] = 0.0f;

        gemm_pass(smb, g_WbH, g_WbL, 16, d, mbase, nbase, tid, lane);

        const float g = gammas[t], e = etas[t];
#pragma unroll
        for (int mt = 0; mt < 4; ++mt)
#pragma unroll
            for (int nt = 0; nt < 2; ++nt)
#pragma unroll
                for (int rg = 0; rg < 2; ++rg) {
                    const int p = mbase + mt * 16 + eg + rg * 8;
                    const uint32_t ncb = (uint32_t)((nbase + nt * 8) * 2 + ec * 4);
                    const uint32_t off = (uint32_t)p * 64 + (ncb ^ exor);
                    const int ai = mt * 2 + nt;
                    __half2 hh = *(const __half2*)(smc + XH_OFF + off);
                    __half2 ll = *(const __half2*)(smc + XL_OFF + off);
                    float xo0 = __half2float(__low2half(hh)) + __half2float(__low2half(ll));
                    float xo1 = __half2float(__high2half(hh)) + __half2float(__high2half(ll));
                    float v0 = fmaf(g, ay[ai][rg * 2 + 0] - d[ai][rg * 2 + 0], xo0);
                    float v1 = fmaf(g, ay[ai][rg * 2 + 1] - d[ai][rg * 2 + 1], xo1);
                    float x0 = copysignf(fmaxf(fabsf(v0) - e, 0.0f), v0);
                    float x1 = copysignf(fmaxf(fabsf(v1) - e, 0.0f), v1);
                    __half h0 = __float2half_rn(x0), h1 = __float2half_rn(x1);
                    __half l0 = __float2half_rn(x0 - __half2float(h0));
                    __half l1 = __float2half_rn(x1 - __half2float(h1));
                    *(__half2*)(smc + XH_OFF + off) = __halves2half2(h0, h1);
                    *(__half2*)(smc + XL_OFF + off) = __halves2half2(l0, l1);
                }
    }

    __syncthreads();
    // output: out[b][m][c] = x[p = c*256 + m], coalesced fp32 writes
    for (int idx = tid; idx < NB * 512; idx += THREADS) {
        const int n = idx >> 9, i = idx & 511, m = i >> 1, cc = i & 1;
        const int p = cc * 256 + m;
        const uint32_t off = swz64(p, n * 2);
        const float v = __half2float(*(const __half*)(smc + XH_OFF + off))
                      + __half2float(*(const __half*)(smc + XL_OFF + off));
        out[(b0 + n) * 512 + i] = v;
    }
}

extern "C" void kernel_launch(void* const* d_in, const int* in_sizes, int n_in,
                              void* d_out, int out_size) {
    const float* y      = (const float*)d_in[0];
    const float* A      = (const float*)d_in[1];
    const float* B      = (const float*)d_in[2];
    const float* etas   = (const float*)d_in[3];
    const float* gammas = (const float*)d_in[4];
    float* out = (float*)d_out;

    prep_kernel<<<512, 256>>>(A, B);

    cudaFuncSetAttribute(lista_main, cudaFuncAttributeMaxDynamicSharedMemorySize, SMEM_TOTAL);
    lista_main<<<NCTA, THREADS, SMEM_TOTAL>>>(y, etas, gammas, out);
}

// round 6
// speedup vs baseline: 1.5751x; 1.0346x over previous
#include <cuda_runtime.h>
#include <cuda_fp16.h>
#include <cstdint>

#define TT        10
#define NB        32                 // batch rows per CTA
#define THREADS   512
#define NCTA      (65536 / NB)       // 2048

// smem layout (bytes)
#define XH_OFF    0                  // x hi: 512 k-rows x 32 n x 2B = 32KB
#define XL_OFF    32768
#define W_OFF     65536              // 2 bufs x (Wh 32KB + Wl 32KB)
#define SMEM_TOTAL (65536 + 2 * 65536)   // 192KB

// W chunk arrays, pre-swizzled: chunk = K-slab of 32, layout [p=512][kk=32] halves
__device__ __half g_WbH[16 * 16384];   // 512KB
__device__ __half g_WbL[16 * 16384];
__device__ __half g_WaH[8 * 16384];    // 256KB
__device__ __half g_WaL[8 * 16384];

// ---------------- PTX helpers ----------------
static __device__ __forceinline__ uint32_t smem_u32(const void* p) {
    uint32_t a;
    asm("{ .reg .u64 t; cvta.to.shared.u64 t, %1; cvt.u32.u64 %0, t; }" : "=r"(a) : "l"(p));
    return a;
}
static __device__ __forceinline__ void cp16(uint32_t s, const void* g) {
    asm volatile("cp.async.cg.shared.global [%0], [%1], 16;" :: "r"(s), "l"(g));
}
static __device__ __forceinline__ void ldmA4(uint32_t* r, uint32_t addr) {
    asm volatile("ldmatrix.sync.aligned.m8n8.x4.shared.b16 {%0,%1,%2,%3}, [%4];"
                 : "=r"(r[0]), "=r"(r[1]), "=r"(r[2]), "=r"(r[3]) : "r"(addr));
}
static __device__ __forceinline__ void ldmB4(uint32_t* r, uint32_t addr) {
    asm volatile("ldmatrix.sync.aligned.m8n8.x4.trans.shared.b16 {%0,%1,%2,%3}, [%4];"
                 : "=r"(r[0]), "=r"(r[1]), "=r"(r[2]), "=r"(r[3]) : "r"(addr));
}
static __device__ __forceinline__ void mma16816(float* d, const uint32_t* a, const uint32_t* b) {
    asm volatile("mma.sync.aligned.m16n8k16.row.col.f32.f16.f16.f32 "
                 "{%0,%1,%2,%3}, {%4,%5,%6,%7}, {%8,%9}, {%0,%1,%2,%3};"
                 : "+f"(d[0]), "+f"(d[1]), "+f"(d[2]), "+f"(d[3])
                 : "r"(a[0]), "r"(a[1]), "r"(a[2]), "r"(a[3]), "r"(b[0]), "r"(b[1]));
}
// fp16-accumulate variant for the small correction terms (2x rate)
static __device__ __forceinline__ void mma16816h(uint32_t* c, const uint32_t* a, const uint32_t* b) {
    asm volatile("mma.sync.aligned.m16n8k16.row.col.f16.f16.f16.f16 "
                 "{%0,%1}, {%2,%3,%4,%5}, {%6,%7}, {%0,%1};"
                 : "+r"(c[0]), "+r"(c[1])
                 : "r"(a[0]), "r"(a[1]), "r"(a[2]), "r"(a[3]), "r"(b[0]), "r"(b[1]));
}

// Swizzle for 64B rows: XOR 16B-slot bits [5:4] with row bits [2:1].
static __device__ __host__ __forceinline__ uint32_t swz64(int row, int colbyte) {
    return (uint32_t)(row * 64 + (colbyte ^ ((row & 6) << 3)));
}

// ---------------- prep: expand complex A,B -> fp16 hi/lo swizzled chunks ----------------
__global__ void prep_kernel(const float* __restrict__ A, const float* __restrict__ B) {
    for (int i = blockIdx.x * blockDim.x + threadIdx.x; i < 393216;
         i += gridDim.x * blockDim.x) {
        float v;
        int dest;
        __half *dH, *dL;
        if (i < 262144) {                        // B matrix: 16 chunks
            int chunk = i >> 14, inner = i & 16383, p = inner >> 5, kk = inner & 31;
            int k = chunk * 32 + kk;
            if (k < 256) v = (p < 256) ? B[p * 256 + k] : B[65536 + (p - 256) * 256 + k];
            else { int q = k - 256; v = (p < 256) ? -B[65536 + p * 256 + q] : B[(p - 256) * 256 + q]; }
            dest = chunk * 16384 + (int)(swz64(p, kk * 2) >> 1);
            dH = g_WbH; dL = g_WbL;
        } else {                                  // A matrix: 8 chunks
            int j = i - 262144;
            int chunk = j >> 14, inner = j & 16383, p = inner >> 5, kk = inner & 31;
            int k = chunk * 32 + kk;
            if (k < 128) v = (p < 256) ? A[p * 128 + k] : A[32768 + (p - 256) * 128 + k];
            else { int q = k - 128; v = (p < 256) ? -A[32768 + p * 128 + q] : A[(p - 256) * 128 + q]; }
            dest = chunk * 16384 + (int)(swz64(p, kk * 2) >> 1);
            dH = g_WaH; dL = g_WaL;
        }
        __half hi = __float2half_rn(v);
        dH[dest] = hi;
        dL[dest] = __float2half_rn(v - __half2float(hi));
    }
}

// ---------------- chunk loader: 64KB (Wh + Wl) via cp.async ----------------
static __device__ __forceinline__ void issue_chunk(uint32_t sbuf, const __half* gH,
                                                   const __half* gL, int c, int tid) {
    const char* srcH = (const char*)gH + (size_t)c * 32768;
    const char* srcL = (const char*)gL + (size_t)c * 32768;
#pragma unroll
    for (int u = 0; u < 4; ++u) {
        uint32_t o = (uint32_t)tid * 16 + (uint32_t)u * 8192;
        cp16(sbuf + o, srcH + o);
        cp16(sbuf + 32768 + o, srcL + o);
    }
}

// ---------------- GEMM pass: 16M x 1N warp tiling, split-precision terms ----------------
// acc[mt*4+nt][4] fp32; corrections accumulated in fp16 and folded at the end.
static __device__ __forceinline__ void gemm_pass(
    uint32_t smb, const __half* gH, const __half* gL, int NC,
    float (*acc)[4], int mbase, int tid, int lane)
{
    issue_chunk(smb + W_OFF, gH, gL, 0, tid);
    asm volatile("cp.async.commit_group;" ::: "memory");
    issue_chunk(smb + W_OFF + 65536, gH, gL, 1, tid);
    asm volatile("cp.async.commit_group;" ::: "memory");

    const int l15 = lane & 15;
    const uint32_t axor = (uint32_t)((l15 & 6) << 3);
    const uint32_t bxor = (uint32_t)((lane & 6) << 3);
    const uint32_t brow = ((uint32_t)(lane & 7) + ((uint32_t)((lane >> 3) & 1)) * 8) * 64;
    const uint32_t bcol0 = (((uint32_t)(lane >> 4) * 16)) ^ bxor;        // n 0..15
    const uint32_t bcol1 = (32u + (uint32_t)(lane >> 4) * 16) ^ bxor;    // n 16..31
    const uint32_t arow0 = (uint32_t)(mbase + l15) * 64;
    const uint32_t arow1 = (uint32_t)(mbase + 16 + l15) * 64;

    uint32_t cacc[8][2];
#pragma unroll
    for (int i = 0; i < 8; ++i) { cacc[i][0] = 0u; cacc[i][1] = 0u; }

#pragma unroll 1
    for (int c = 0; c < NC; ++c) {
        asm volatile("cp.async.wait_group 1;" ::: "memory");
        __syncthreads();
        const uint32_t wb = smb + W_OFF + (uint32_t)(c & 1) * 65536;
#pragma unroll
        for (int s = 0; s < 2; ++s) {
            const uint32_t acol = ((uint32_t)(s * 32 + ((lane >> 4) * 16))) ^ axor;
            const uint32_t xrow = smb + (uint32_t)(c * 32 + s * 16) * 64 + brow;

            uint32_t bh[8], ah[2][4];
            ldmB4(bh,     xrow + bcol0);
            ldmB4(bh + 4, xrow + bcol1);
            ldmA4(ah[0], wb + arow0 + acol);
            ldmA4(ah[1], wb + arow1 + acol);
            // main term: Wh * xh, fp32 accumulate
#pragma unroll
            for (int mt = 0; mt < 2; ++mt)
#pragma unroll
                for (int nt = 0; nt < 4; ++nt)
                    mma16816(acc[mt * 4 + nt], ah[mt], &bh[nt * 2]);

            uint32_t bl[8];
            ldmB4(bl,     xrow + 32768 + bcol0);
            ldmB4(bl + 4, xrow + 32768 + bcol1);
            // correction: Wh * xl, fp16 accumulate
#pragma unroll
            for (int mt = 0; mt < 2; ++mt)
#pragma unroll
                for (int nt = 0; nt < 4; ++nt)
                    mma16816h(cacc[mt * 4 + nt], ah[mt], &bl[nt * 2]);

            uint32_t al[2][4];
            ldmA4(al[0], wb + 32768 + arow0 + acol);
            ldmA4(al[1], wb + 32768 + arow1 + acol);
            // correction: Wl * xh, fp16 accumulate
#pragma unroll
            for (int mt = 0; mt < 2; ++mt)
#pragma unroll
                for (int nt = 0; nt < 4; ++nt)
                    mma16816h(cacc[mt * 4 + nt], al[mt], &bh[nt * 2]);
        }
        __syncthreads();
        if (c + 2 < NC) issue_chunk(wb, gH, gL, c + 2, tid);
        asm volatile("cp.async.commit_group;" ::: "memory");
    }

    // fold fp16 corrections into fp32 accumulators
#pragma unroll
    for (int i = 0; i < 8; ++i) {
        float2 f0 = __half22float2(*(const __half2*)&cacc[i][0]);
        float2 f1 = __half22float2(*(const __half2*)&cacc[i][1]);
        acc[i][0] += f0.x; acc[i][1] += f0.y;
        acc[i][2] += f1.x; acc[i][3] += f1.y;
    }
}

// ---------------- main fused kernel ----------------
__global__ __launch_bounds__(THREADS, 1)
void lista_main(const float* __restrict__ y,
                const float* __restrict__ etas,
                const float* __restrict__ gammas,
                float* __restrict__ out) {
    extern __shared__ char smc[];
    const uint32_t smb = smem_u32(smc);
    const int tid = threadIdx.x, lane = tid & 31, wid = tid >> 5;
    const int mbase = wid * 32;               // 16 M-warps x 32 rows, full N=32
    const long b0 = (long)blockIdx.x * NB;

    // stage y into x planes (rows 0..255): k = c*128 + q
    for (int idx = tid; idx < NB * 256; idx += THREADS) {
        int n = idx >> 8, j = idx & 255, q = j >> 1, cc = j & 1, k = cc * 128 + q;
        float v = y[(b0 + n) * 256 + j];
        __half hi = __float2half_rn(v);
        __half lo = __float2half_rn(v - __half2float(hi));
        uint32_t off = swz64(k, n * 2);
        *(__half*)(smc + XH_OFF + off) = hi;
        *(__half*)(smc + XL_OFF + off) = lo;
    }
    __syncthreads();

    float ay[8][4], d[8][4];
#pragma unroll
    for (int i = 0; i < 8; ++i)
#pragma unroll
        for (int j = 0; j < 4; ++j) ay[i][j] = 0.0f;

    // epilogue lane geometry
    const int eg = lane >> 2, ec = lane & 3;
    const uint32_t exor = (uint32_t)((eg & 6) << 3);

    // -------- Phase A: Ay = Wa * y (resident in regs) --------
    gemm_pass(smb, g_WaH, g_WaL, 8, ay, mbase, tid, lane);
    {
        const float g = gammas[0], e = etas[0];
#pragma unroll
        for (int mt = 0; mt < 2; ++mt)
#pragma unroll
            for (int nt = 0; nt < 4; ++nt)
#pragma unroll
                for (int rg = 0; rg < 2; ++rg) {
                    const int p = mbase + mt * 16 + eg + rg * 8;
                    const uint32_t off = (uint32_t)p * 64
                                       + (((uint32_t)(16 * nt + 4 * ec)) ^ exor);
                    const int ai = mt * 4 + nt;
                    float v0 = g * ay[ai][rg * 2 + 0];
                    float v1 = g * ay[ai][rg * 2 + 1];
                    float x0 = copysignf(fmaxf(fabsf(v0) - e, 0.0f), v0);
                    float x1 = copysignf(fmaxf(fabsf(v1) - e, 0.0f), v1);
                    __half h0 = __float2half_rn(x0), h1 = __float2half_rn(x1);
                    __half l0 = __float2half_rn(x0 - __half2float(h0));
                    __half l1 = __float2half_rn(x1 - __half2float(h1));
                    *(__half2*)(smc + XH_OFF + off) = __halves2half2(h0, h1);
                    *(__half2*)(smc + XL_OFF + off) = __halves2half2(l0, l1);
                }
    }
    // next gemm's first barrier orders these writes vs ldmatrix reads

    // -------- 10 iterations: x = shrink(x + g*(Ay - Bx), e) --------
#pragma unroll 1
    for (int t = 1; t <= TT; ++t) {
#pragma unroll
        for (int i = 0; i < 8; ++i)
#pragma unroll
            for (int j = 0; j < 4; ++j) d[i][j] = 0.0f;

        gemm_pass(smb, g_WbH, g_WbL, 16, d, mbase, tid, lane);

        const float g = gammas[t], e = etas[t];
#pragma unroll
        for (int mt = 0; mt < 2; ++mt)
#pragma unroll
            for (int nt = 0; nt < 4; ++nt)
#pragma unroll
                for (int rg = 0; rg < 2; ++rg) {
                    const int p = mbase + mt * 16 + eg + rg * 8;
                    const uint32_t off = (uint32_t)p * 64
                                       + (((uint32_t)(16 * nt + 4 * ec)) ^ exor);
                    const int ai = mt * 4 + nt;
                    __half2 hh = *(const __half2*)(smc + XH_OFF + off);
                    __half2 ll = *(const __half2*)(smc + XL_OFF + off);
                    float2 fh = __half22float2(hh), fl = __half22float2(ll);
                    float v0 = fmaf(g, ay[ai][rg * 2 + 0] - d[ai][rg * 2 + 0], fh.x + fl.x);
                    float v1 = fmaf(g, ay[ai][rg * 2 + 1] - d[ai][rg * 2 + 1], fh.y + fl.y);
                    float x0 = copysignf(fmaxf(fabsf(v0) - e, 0.0f), v0);
                    float x1 = copysignf(fmaxf(fabsf(v1) - e, 0.0f), v1);
                    __half h0 = __float2half_rn(x0), h1 = __float2half_rn(x1);
                    __half l0 = __float2half_rn(x0 - __half2float(h0));
                    __half l1 = __float2half_rn(x1 - __half2float(h1));
                    *(__half2*)(smc + XH_OFF + off) = __halves2half2(h0, h1);
                    *(__half2*)(smc + XL_OFF + off) = __halves2half2(l0, l1);
                }
    }

    __syncthreads();
    // output: out[b][m][c] = x[p = c*256 + m], coalesced fp32 writes
    for (int idx = tid; idx < NB * 512; idx += THREADS) {
        const int n = idx >> 9, i = idx & 511, m = i >> 1, cc = i & 1;
        const int p = cc * 256 + m;
        const uint32_t off = swz64(p, n * 2);
        const float v = __half2float(*(const __half*)(smc + XH_OFF + off))
                      + __half2float(*(const __half*)(smc + XL_OFF + off));
        out[(b0 + n) * 512 + i] = v;
    }
}

extern "C" void kernel_launch(void* const* d_in, const int* in_sizes, int n_in,
                              void* d_out, int out_size) {
    const float* y      = (const float*)d_in[0];
    const float* A      = (const float*)d_in[1];
    const float* B      = (const float*)d_in[2];
    const float* etas   = (const float*)d_in[3];
    const float* gammas = (const float*)d_in[4];
    float* out = (float*)d_out;

    prep_kernel<<<512, 256>>>(A, B);

    cudaFuncSetAttribute(lista_main, cudaFuncAttributeMaxDynamicSharedMemorySize, SMEM_TOTAL);
    lista_main<<<NCTA, THREADS, SMEM_TOTAL>>>(y, etas, gammas, out);
}

// round 7
// speedup vs baseline: 1.9290x; 1.2247x over previous
#include <cuda_runtime.h>
#include <cuda_fp16.h>
#include <cstdint>

#define TT        10
#define NB        32                 // batch rows per CTA
#define THREADS   512
#define NCTA      (65536 / NB)       // 2048

// smem layout (bytes)
#define XH_OFF    0                  // x hi: 512 k-rows x 32 n x 2B = 32KB
#define XL_OFF    32768
#define AY_OFF    65536              // Ay: per-thread 33-float padded rows
#define SMEM_TOTAL (65536 + 512 * 33 * 4)   // 133120

// W in MMA-fragment order: uint4 index ((chunk16*32 + mtile)*32 + lane),
// halfs within = {a0..a7} of mma.m16n8k16 A fragment.
__device__ __half g_WbH[262144];   // 512KB  (32 chunks)
__device__ __half g_WbL[262144];
__device__ __half g_WaH[131072];   // 256KB  (16 chunks)
__device__ __half g_WaL[131072];

// ---------------- PTX helpers ----------------
static __device__ __forceinline__ uint32_t smem_u32(const void* p) {
    uint32_t a;
    asm("{ .reg .u64 t; cvta.to.shared.u64 t, %1; cvt.u32.u64 %0, t; }" : "=r"(a) : "l"(p));
    return a;
}
static __device__ __forceinline__ void ldmB4(uint32_t* r, uint32_t addr) {
    asm volatile("ldmatrix.sync.aligned.m8n8.x4.trans.shared.b16 {%0,%1,%2,%3}, [%4];"
                 : "=r"(r[0]), "=r"(r[1]), "=r"(r[2]), "=r"(r[3]) : "r"(addr));
}
static __device__ __forceinline__ void mma16816(float* d, const uint32_t* a, const uint32_t* b) {
    asm volatile("mma.sync.aligned.m16n8k16.row.col.f32.f16.f16.f32 "
                 "{%0,%1,%2,%3}, {%4,%5,%6,%7}, {%8,%9}, {%0,%1,%2,%3};"
                 : "+f"(d[0]), "+f"(d[1]), "+f"(d[2]), "+f"(d[3])
                 : "r"(a[0]), "r"(a[1]), "r"(a[2]), "r"(a[3]), "r"(b[0]), "r"(b[1]));
}
static __device__ __forceinline__ void mma16816h(uint32_t* c, const uint32_t* a, const uint32_t* b) {
    asm volatile("mma.sync.aligned.m16n8k16.row.col.f16.f16.f16.f16 "
                 "{%0,%1}, {%2,%3,%4,%5}, {%6,%7}, {%0,%1};"
                 : "+r"(c[0]), "+r"(c[1])
                 : "r"(a[0]), "r"(a[1]), "r"(a[2]), "r"(a[3]), "r"(b[0]), "r"(b[1]));
}

// Swizzle for 64B rows (x planes): XOR 16B-slot bits [5:4] with row bits [2:1].
static __device__ __host__ __forceinline__ uint32_t swz64(int row, int colbyte) {
    return (uint32_t)(row * 64 + (colbyte ^ ((row & 6) << 3)));
}

// ---------------- prep: expand complex A,B -> fp16 hi/lo FRAGMENT-ORDER arrays ----------------
__global__ void prep_kernel(const float* __restrict__ A, const float* __restrict__ B) {
    const int NBEL = 512 * 512, NAEL = 512 * 256;
    for (int i = blockIdx.x * blockDim.x + threadIdx.x; i < NBEL + NAEL;
         i += gridDim.x * blockDim.x) {
        float v;
        __half *dH, *dL;
        int p, k;
        if (i < NBEL) {
            p = i >> 9; k = i & 511;
            if (k < 256) v = (p < 256) ? B[p * 256 + k] : B[65536 + (p - 256) * 256 + k];
            else { int q = k - 256; v = (p < 256) ? -B[65536 + p * 256 + q] : B[(p - 256) * 256 + q]; }
            dH = g_WbH; dL = g_WbL;
        } else {
            int j = i - NBEL;
            p = j >> 8; k = j & 255;
            if (k < 128) v = (p < 256) ? A[p * 128 + k] : A[32768 + (p - 256) * 128 + k];
            else { int q = k - 128; v = (p < 256) ? -A[32768 + p * 128 + q] : A[(p - 256) * 128 + q]; }
            dH = g_WaH; dL = g_WaL;
        }
        // fragment-order destination
        const int chunk = k >> 4, kk = k & 15, mt = p >> 4, row = p & 15;
        const int rr = (row >= 8 ? 1 : 0) + (kk >= 8 ? 2 : 0);
        const int t = (kk & 7) >> 1, pos = kk & 1;
        const int lane = (row & 7) * 4 + t;
        const int dest = ((chunk * 32 + mt) * 32 + lane) * 8 + rr * 2 + pos;
        __half hi = __float2half_rn(v);
        dH[dest] = hi;
        dL[dest] = __float2half_rn(v - __half2float(hi));
    }
}

// load A fragments (H mt0, H mt1, L mt0, L mt1) for one K16 chunk
static __device__ __forceinline__ void ldA(uint4* Ar, const uint4* gH, const uint4* gL, int idx) {
    Ar[0] = __ldg(gH + idx);
    Ar[1] = __ldg(gH + idx + 32);
    Ar[2] = __ldg(gL + idx);
    Ar[3] = __ldg(gL + idx + 32);
}

// ---------------- GEMM pass: A from global (fragment LDG), B from smem x planes ----------------
static __device__ __forceinline__ void gemm_pass(
    const char* smc, const __half* gHh, const __half* gLh, int NC,
    float (*acc)[4], int mt0, int lane)
{
    const uint4* gH = (const uint4*)gHh;
    const uint4* gL = (const uint4*)gLh;
    const uint32_t smb = smem_u32(smc);
    const uint32_t bxor = (uint32_t)((lane & 6) << 3);
    const uint32_t brow = ((uint32_t)(lane & 7) + ((uint32_t)((lane >> 3) & 1)) * 8) * 64;
    const uint32_t bcol0 = (((uint32_t)(lane >> 4) * 16)) ^ bxor;        // n 0..15
    const uint32_t bcol1 = (32u + (uint32_t)(lane >> 4) * 16) ^ bxor;    // n 16..31

    uint32_t cacc[8][2];
#pragma unroll
    for (int i = 0; i < 8; ++i) { cacc[i][0] = 0u; cacc[i][1] = 0u; }

    const int idx = mt0 * 32 + lane;
    uint4 A0[4], A1[4];
    ldA(A0, gH, gL, idx);
    ldA(A1, gH, gL, idx + 1024);

#pragma unroll 1
    for (int c = 0; c < NC; c += 2) {
        // ---- even chunk c : uses A0 ----
        {
            const uint32_t xrow = smb + ((uint32_t)c << 10) + brow;
            uint32_t bh[8], bl[8];
            ldmB4(bh,     xrow + bcol0);
            ldmB4(bh + 4, xrow + bcol1);
            ldmB4(bl,     xrow + 32768u + bcol0);
            ldmB4(bl + 4, xrow + 32768u + bcol1);
            const uint32_t* ah0 = (const uint32_t*)&A0[0];
            const uint32_t* ah1 = (const uint32_t*)&A0[1];
            const uint32_t* al0 = (const uint32_t*)&A0[2];
            const uint32_t* al1 = (const uint32_t*)&A0[3];
#pragma unroll
            for (int nt = 0; nt < 4; ++nt) {
                mma16816(acc[nt],     ah0, &bh[nt * 2]);
                mma16816(acc[4 + nt], ah1, &bh[nt * 2]);
            }
#pragma unroll
            for (int nt = 0; nt < 4; ++nt) {
                mma16816h(cacc[nt],     ah0, &bl[nt * 2]);
                mma16816h(cacc[4 + nt], ah1, &bl[nt * 2]);
            }
#pragma unroll
            for (int nt = 0; nt < 4; ++nt) {
                mma16816h(cacc[nt],     al0, &bh[nt * 2]);
                mma16816h(cacc[4 + nt], al1, &bh[nt * 2]);
            }
        }
        if (c + 2 < NC) ldA(A0, gH, gL, idx + (c + 2) * 1024);
        // ---- odd chunk c+1 : uses A1 ----
        {
            const uint32_t xrow = smb + ((uint32_t)(c + 1) << 10) + brow;
            uint32_t bh[8], bl[8];
            ldmB4(bh,     xrow + bcol0);
            ldmB4(bh + 4, xrow + bcol1);
            ldmB4(bl,     xrow + 32768u + bcol0);
            ldmB4(bl + 4, xrow + 32768u + bcol1);
            const uint32_t* ah0 = (const uint32_t*)&A1[0];
            const uint32_t* ah1 = (const uint32_t*)&A1[1];
            const uint32_t* al0 = (const uint32_t*)&A1[2];
            const uint32_t* al1 = (const uint32_t*)&A1[3];
#pragma unroll
            for (int nt = 0; nt < 4; ++nt) {
                mma16816(acc[nt],     ah0, &bh[nt * 2]);
                mma16816(acc[4 + nt], ah1, &bh[nt * 2]);
            }
#pragma unroll
            for (int nt = 0; nt < 4; ++nt) {
                mma16816h(cacc[nt],     ah0, &bl[nt * 2]);
                mma16816h(cacc[4 + nt], ah1, &bl[nt * 2]);
            }
#pragma unroll
            for (int nt = 0; nt < 4; ++nt) {
                mma16816h(cacc[nt],     al0, &bh[nt * 2]);
                mma16816h(cacc[4 + nt], al1, &bh[nt * 2]);
            }
        }
        if (c + 3 < NC) ldA(A1, gH, gL, idx + (c + 3) * 1024);
    }

    // fold fp16 corrections into fp32 accumulators
#pragma unroll
    for (int i = 0; i < 8; ++i) {
        float2 f0 = __half22float2(*(const __half2*)&cacc[i][0]);
        float2 f1 = __half22float2(*(const __half2*)&cacc[i][1]);
        acc[i][0] += f0.x; acc[i][1] += f0.y;
        acc[i][2] += f1.x; acc[i][3] += f1.y;
    }
}

// ---------------- main fused kernel ----------------
__global__ __launch_bounds__(THREADS, 1)
void lista_main(const float* __restrict__ y,
                const float* __restrict__ etas,
                const float* __restrict__ gammas,
                float* __restrict__ out) {
    extern __shared__ char smc[];
    const int tid = threadIdx.x, lane = tid & 31, wid = tid >> 5;
    const int mbase = wid * 32;               // 16 M-warps x 32 rows, full N=32
    const int mt0 = wid * 2;                  // first mtile index
    const long b0 = (long)blockIdx.x * NB;
    float* ays = (float*)(smc + AY_OFF);

    // stage y into x planes (rows 0..255): k = c*128 + q
    for (int idx = tid; idx < NB * 256; idx += THREADS) {
        int n = idx >> 8, j = idx & 255, q = j >> 1, cc = j & 1, k = cc * 128 + q;
        float v = y[(b0 + n) * 256 + j];
        __half hi = __float2half_rn(v);
        __half lo = __float2half_rn(v - __half2float(hi));
        uint32_t off = swz64(k, n * 2);
        *(__half*)(smc + XH_OFF + off) = hi;
        *(__half*)(smc + XL_OFF + off) = lo;
    }
    __syncthreads();

    float d[8][4];
#pragma unroll
    for (int i = 0; i < 8; ++i)
#pragma unroll
        for (int j = 0; j < 4; ++j) d[i][j] = 0.0f;

    // epilogue lane geometry
    const int eg = lane >> 2, ec = lane & 3;
    const uint32_t exor = (uint32_t)((eg & 6) << 3);

    // -------- Phase A: Ay = Wa * y --------
    gemm_pass(smc, g_WaH, g_WaL, 16, d, mt0, lane);
    __syncthreads();   // all warps done reading y-planes
    {
        const float g = gammas[0], e = etas[0];
#pragma unroll
        for (int mt = 0; mt < 2; ++mt)
#pragma unroll
            for (int nt = 0; nt < 4; ++nt)
#pragma unroll
                for (int rg = 0; rg < 2; ++rg) {
                    const int p = mbase + mt * 16 + eg + rg * 8;
                    const uint32_t off = (uint32_t)p * 64
                                       + (((uint32_t)(16 * nt + 4 * ec)) ^ exor);
                    const int ai = mt * 4 + nt;
                    const int r = ai * 4 + rg * 2;
                    ays[tid * 33 + r]     = d[ai][rg * 2 + 0];
                    ays[tid * 33 + r + 1] = d[ai][rg * 2 + 1];
                    float v0 = g * d[ai][rg * 2 + 0];
                    float v1 = g * d[ai][rg * 2 + 1];
                    float x0 = copysignf(fmaxf(fabsf(v0) - e, 0.0f), v0);
                    float x1 = copysignf(fmaxf(fabsf(v1) - e, 0.0f), v1);
                    __half h0 = __float2half_rn(x0), h1 = __float2half_rn(x1);
                    __half l0 = __float2half_rn(x0 - __half2float(h0));
                    __half l1 = __float2half_rn(x1 - __half2float(h1));
                    *(__half2*)(smc + XH_OFF + off) = __halves2half2(h0, h1);
                    *(__half2*)(smc + XL_OFF + off) = __halves2half2(l0, l1);
                }
    }
    __syncthreads();

    // -------- 10 iterations: x = shrink(x + g*(Ay - Bx), e) --------
#pragma unroll 1
    for (int t = 1; t <= TT; ++t) {
#pragma unroll
        for (int i = 0; i < 8; ++i)
#pragma unroll
            for (int j = 0; j < 4; ++j) d[i][j] = 0.0f;

        gemm_pass(smc, g_WbH, g_WbL, 32, d, mt0, lane);
        __syncthreads();   // all warps done reading x planes

        const float g = gammas[t], e = etas[t];
#pragma unroll
        for (int mt = 0; mt < 2; ++mt)
#pragma unroll
            for (int nt = 0; nt < 4; ++nt)
#pragma unroll
                for (int rg = 0; rg < 2; ++rg) {
                    const int p = mbase + mt * 16 + eg + rg * 8;
                    const uint32_t off = (uint32_t)p * 64
                                       + (((uint32_t)(16 * nt + 4 * ec)) ^ exor);
                    const int ai = mt * 4 + nt;
                    const int r = ai * 4 + rg * 2;
                    const float ay0 = ays[tid * 33 + r];
                    const float ay1 = ays[tid * 33 + r + 1];
                    __half2 hh = *(const __half2*)(smc + XH_OFF + off);
                    __half2 ll = *(const __half2*)(smc + XL_OFF + off);
                    float2 fh = __half22float2(hh), fl = __half22float2(ll);
                    float v0 = fmaf(g, ay0 - d[ai][rg * 2 + 0], fh.x + fl.x);
                    float v1 = fmaf(g, ay1 - d[ai][rg * 2 + 1], fh.y + fl.y);
                    float x0 = copysignf(fmaxf(fabsf(v0) - e, 0.0f), v0);
                    float x1 = copysignf(fmaxf(fabsf(v1) - e, 0.0f), v1);
                    __half h0 = __float2half_rn(x0), h1 = __float2half_rn(x1);
                    __half l0 = __float2half_rn(x0 - __half2float(h0));
                    __half l1 = __float2half_rn(x1 - __half2float(h1));
                    *(__half2*)(smc + XH_OFF + off) = __halves2half2(h0, h1);
                    *(__half2*)(smc + XL_OFF + off) = __halves2half2(l0, l1);
                }
        __syncthreads();
    }

    // output: out[b][m][c] = x[p = c*256 + m], coalesced fp32 writes
    for (int idx = tid; idx < NB * 512; idx += THREADS) {
        const int n = idx >> 9, i = idx & 511, m = i >> 1, cc = i & 1;
        const int p = cc * 256 + m;
        const uint32_t off = swz64(p, n * 2);
        const float v = __half2float(*(const __half*)(smc + XH_OFF + off))
                      + __half2float(*(const __half*)(smc + XL_OFF + off));
        out[(b0 + n) * 512 + i] = v;
    }
}

extern "C" void kernel_launch(void* const* d_in, const int* in_sizes, int n_in,
                              void* d_out, int out_size) {
    const float* y      = (const float*)d_in[0];
    const float* A      = (const float*)d_in[1];
    const float* B      = (const float*)d_in[2];
    const float* etas   = (const float*)d_in[3];
    const float* gammas = (const float*)d_in[4];
    float* out = (float*)d_out;

    prep_kernel<<<512, 256>>>(A, B);

    cudaFuncSetAttribute(lista_main, cudaFuncAttributeMaxDynamicSharedMemorySize, SMEM_TOTAL);
    lista_main<<<NCTA, THREADS, SMEM_TOTAL>>>(y, etas, gammas, out);
}